// round 13
// baseline (speedup 1.0000x reference)
#include <cuda_runtime.h>
#include <cuda_fp16.h>
#include <math.h>

#define MAX_N 100000
#define MAX_E 1600000
#define D 64
#define SCAN_B 1024

// ---- device scratch (no cudaMalloc allowed) --------------------------------
// g_count is zero at module load; scatter_kernel re-zeroes it every launch
// (after its last reader ran), so every launch sees zeros.
__device__ __align__(16) __half g_qh[MAX_N * D];   // q  fp16, 128B/row
__device__ __align__(16) __half g_kh[MAX_N * D];   // k*tau fp16
__device__ __align__(16) __half g_vh[MAX_N * D];   // v  fp16
__device__ int   g_count[MAX_N + 1];
__device__ int   g_rowptr[MAX_N + 1];
__device__ int   g_cursor[MAX_N + 1];
__device__ int   g_bsum[128];
__device__ int   g_srcs[MAX_E];         // src node, clustered by dst (CSR order)
__device__ int   g_eids[MAX_E];         // original edge id, CSR order
__device__ float g_exc[MAX_E];          // ex in CSR order (coalesced)
__device__ float g_ex[MAX_E];           // fallback if out has no alpha slot

// ---- packed fp32x2 helpers (Blackwell FFMA2; ptxas never auto-fuses) -------
__device__ __forceinline__ void ffma2(unsigned long long& d,
                                      unsigned long long a,
                                      unsigned long long b) {
    asm("fma.rn.f32x2 %0, %1, %2, %0;" : "+l"(d) : "l"(a), "l"(b));
}
__device__ __forceinline__ unsigned long long pack2(float lo, float hi) {
    unsigned long long r;
    asm("mov.b64 %0, {%1, %2};" : "=l"(r) : "f"(lo), "f"(hi));
    return r;
}
__device__ __forceinline__ float2 unpack2(unsigned long long a) {
    float2 u;
    asm("mov.b64 {%0, %1}, %2;" : "=f"(u.x), "=f"(u.y) : "l"(a));
    return u;
}

// ---------------------------------------------------------------------------
// K1: q,k,v = z @ W{q,k,v} + b — exact fp32 via packed FFMA2 with NODE-PAIR
// packing (natural LDS.128 z operand, no tile duplication). Per k-step:
// 2x LDS.128 + 4 mov.b64 + 8 FFMA2. tau folded into k; outputs fp16 rows.
// ---------------------------------------------------------------------------
__global__ __launch_bounds__(256) void proj_kernel(
    const float* __restrict__ z,
    const float* __restrict__ Wq, const float* __restrict__ bq,
    const float* __restrict__ Wk, const float* __restrict__ bk,
    const float* __restrict__ Wv, const float* __restrict__ bv,
    int n)
{
    __shared__ __align__(16) float zsh[64 * 68];   // transposed: zsh[k*68 + node]
    __shared__ __align__(16) float wsh[64 * 64];   // wsh[k*64 + dim]

    const int tid = threadIdx.x;
    const int node0 = blockIdx.x * 64;

    for (int i = tid; i < 64 * 64; i += 256) {
        int nn = i >> 6, kk = i & 63;
        int g = node0 + nn;
        zsh[kk * 68 + nn] = (g < n) ? z[(size_t)g * D + kk] : 0.0f;
    }

    const float* Ws[3] = {Wq, Wk, Wv};
    const float* bs[3] = {bq, bk, bv};
    __half* outs[3] = {g_qh, g_kh, g_vh};

    const int ng = tid >> 4;   // node group 0..15 (4 nodes = 2 node-pairs)
    const int dg = tid & 15;   // dim  group 0..15 (4 dims)

    for (int p = 0; p < 3; p++) {
        __syncthreads();
        const float* W = Ws[p];
        for (int i = tid; i < 64 * 64; i += 256) wsh[i] = W[i];
        __syncthreads();

        float4 b4 = *(const float4*)(bs[p] + dg * 4);
        unsigned long long acc2[2][4];
        acc2[0][0] = acc2[1][0] = pack2(b4.x, b4.x);
        acc2[0][1] = acc2[1][1] = pack2(b4.y, b4.y);
        acc2[0][2] = acc2[1][2] = pack2(b4.z, b4.z);
        acc2[0][3] = acc2[1][3] = pack2(b4.w, b4.w);

        #pragma unroll 8
        for (int k = 0; k < 64; k++) {
            ulonglong2 zz = *(const ulonglong2*)&zsh[k * 68 + ng * 4];
            float4 wv = *(const float4*)&wsh[k * 64 + dg * 4];
            unsigned long long w0 = pack2(wv.x, wv.x);
            unsigned long long w1 = pack2(wv.y, wv.y);
            unsigned long long w2 = pack2(wv.z, wv.z);
            unsigned long long w3 = pack2(wv.w, wv.w);
            ffma2(acc2[0][0], zz.x, w0); ffma2(acc2[0][1], zz.x, w1);
            ffma2(acc2[0][2], zz.x, w2); ffma2(acc2[0][3], zz.x, w3);
            ffma2(acc2[1][0], zz.y, w0); ffma2(acc2[1][1], zz.y, w1);
            ffma2(acc2[1][2], zz.y, w2); ffma2(acc2[1][3], zz.y, w3);
        }

        const float scl = (p == 1) ? 0.125f : 1.0f;   // tau into k
        __half* op = outs[p];
        #pragma unroll
        for (int i2 = 0; i2 < 4; i2++) {
            int g = node0 + ng * 4 + i2;
            if (g < n) {
                int pr = i2 >> 1, lo = i2 & 1;
                float2 d0 = unpack2(acc2[pr][0]);
                float2 d1 = unpack2(acc2[pr][1]);
                float2 d2 = unpack2(acc2[pr][2]);
                float2 d3 = unpack2(acc2[pr][3]);
                float e0 = lo ? d0.y : d0.x;
                float e1 = lo ? d1.y : d1.x;
                float e2 = lo ? d2.y : d2.x;
                float e3 = lo ? d3.y : d3.x;
                __half2 h01 = __float22half2_rn(make_float2(e0 * scl, e1 * scl));
                __half2 h23 = __float22half2_rn(make_float2(e2 * scl, e3 * scl));
                uint2 pk;
                pk.x = *(unsigned*)&h01; pk.y = *(unsigned*)&h23;
                *(uint2*)(op + (size_t)g * D + dg * 4) = pk;
            }
        }
    }
}

// ---------------------------------------------------------------------------
// CSR build: hist (int4) -> scan1 (block sums) -> scan3 (scan + per-block
// bsum prefix) -> scatter (int4, also re-zeroes g_count for next launch).
// ---------------------------------------------------------------------------
__global__ void hist_kernel(const int* __restrict__ dst, int E) {
    int e = (blockIdx.x * blockDim.x + threadIdx.x) * 4;
    if (e + 3 < E) {
        int4 d = *(const int4*)(dst + e);
        atomicAdd(&g_count[d.x], 1);
        atomicAdd(&g_count[d.y], 1);
        atomicAdd(&g_count[d.z], 1);
        atomicAdd(&g_count[d.w], 1);
    } else {
        for (int t = e; t < E; t++) atomicAdd(&g_count[dst[t]], 1);
    }
}

__global__ __launch_bounds__(SCAN_B) void scan1_kernel(int len) {
    __shared__ int wsum[32];
    int t = threadIdx.x, lane = t & 31, wid = t >> 5;
    int i = blockIdx.x * SCAN_B + t;
    int v = (i < len) ? g_count[i] : 0;
    #pragma unroll
    for (int off = 16; off > 0; off >>= 1) v += __shfl_xor_sync(0xffffffffu, v, off);
    if (lane == 0) wsum[wid] = v;
    __syncthreads();
    if (wid == 0) {
        int x = wsum[lane];
        #pragma unroll
        for (int off = 16; off > 0; off >>= 1) x += __shfl_xor_sync(0xffffffffu, x, off);
        if (lane == 0) g_bsum[blockIdx.x] = x;
    }
}

__global__ __launch_bounds__(SCAN_B) void scan3_kernel(int len) {
    __shared__ int wsum[32];
    __shared__ int blk_off;
    int t = threadIdx.x, lane = t & 31, wid = t >> 5;

    if (wid == 0) {
        int s = 0;
        for (int b = lane; b < blockIdx.x; b += 32) s += g_bsum[b];
        #pragma unroll
        for (int off = 16; off > 0; off >>= 1) s += __shfl_xor_sync(0xffffffffu, s, off);
        if (lane == 0) blk_off = s;
    }

    int i = blockIdx.x * SCAN_B + t;
    int v = (i < len) ? g_count[i] : 0;
    int incl = v;
    #pragma unroll
    for (int off = 1; off < 32; off <<= 1) {
        int u = __shfl_up_sync(0xffffffffu, incl, off);
        if (lane >= off) incl += u;
    }
    if (lane == 31) wsum[wid] = incl;
    __syncthreads();
    if (wid == 0) {
        int x = wsum[lane];
        #pragma unroll
        for (int off = 1; off < 32; off <<= 1) {
            int u = __shfl_up_sync(0xffffffffu, x, off);
            if (lane >= off) x += u;
        }
        wsum[lane] = x;
    }
    __syncthreads();
    int excl = incl - v + ((wid > 0) ? wsum[wid - 1] : 0) + blk_off;
    if (i < len) { g_rowptr[i] = excl; g_cursor[i] = excl; }
}

__global__ void scatter_kernel(const int* __restrict__ src,
                               const int* __restrict__ dst, int E, int n) {
    int gt = blockIdx.x * blockDim.x + threadIdx.x;
    if (gt <= n) g_count[gt] = 0;   // re-zero histogram for next launch

    int e = gt * 4;
    if (e + 3 < E) {
        int4 s = *(const int4*)(src + e);
        int4 d = *(const int4*)(dst + e);
        int p0 = atomicAdd(&g_cursor[d.x], 1);
        int p1 = atomicAdd(&g_cursor[d.y], 1);
        int p2 = atomicAdd(&g_cursor[d.z], 1);
        int p3 = atomicAdd(&g_cursor[d.w], 1);
        g_srcs[p0] = s.x; g_eids[p0] = e + 0;
        g_srcs[p1] = s.y; g_eids[p1] = e + 1;
        g_srcs[p2] = s.z; g_eids[p2] = e + 2;
        g_srcs[p3] = s.w; g_eids[p3] = e + 3;
    } else {
        for (int t = e; t < E; t++) {
            int pos = atomicAdd(&g_cursor[dst[t]], 1);
            g_srcs[pos] = src[t]; g_eids[pos] = t;
        }
    }
}

// ---------------------------------------------------------------------------
// K2 (fused): one warp per dst node, 8 lanes per edge, 4 edges per iteration,
// with NEXT iteration's src records prefetched so the record-load and kv-load
// latency legs overlap. fp16 HFMA2 dot (tau folded into k), fp32 accumulation.
// ex written coalesced to CSR-ordered buffer; epilogue scatters alpha=ex*rden
// (eids read coalesced) and stores h. NO atomics, NO smem.
// Segment-max skipped: alpha shift-invariant, |e|<~6 -> exp safe.
// ---------------------------------------------------------------------------
__global__ __launch_bounds__(256) void fused_attn_kernel(
    float* __restrict__ exbuf, float* __restrict__ h, int n)
{
    int wid = threadIdx.x >> 5;
    int w = blockIdx.x * 8 + wid;
    if (w >= n) return;
    int lane = threadIdx.x & 31;
    int grp  = lane >> 3;        // edge group 0..3
    int ch   = lane & 7;         // 8-half chunk of the 64-dim row

    int beg = __ldg(&g_rowptr[w]);
    int end = __ldg(&g_rowptr[w + 1]);
    int cnt = end - beg;

    uint4 qraw = *(const uint4*)(g_qh + (size_t)w * D + ch * 8);
    __half2 q0 = *(__half2*)&qraw.x, q1 = *(__half2*)&qraw.y,
            q2 = *(__half2*)&qraw.z, q3 = *(__half2*)&qraw.w;

    float den = 0.0f;
    float acc[8];
    #pragma unroll
    for (int j = 0; j < 8; j++) acc[j] = 0.0f;

    // prefetched src record for this group's current edge
    int sP = (beg + grp < end) ? g_srcs[beg + grp] : 0;

    for (int i = beg; i < end; i += 4) {
        int idx = i + grp;
        bool ok = idx < end;
        int sC = sP;                                   // consume prefetch
        int nidx = idx + 4;
        sP = (nidx < end) ? g_srcs[nidx] : 0;          // prefetch next iter

        uint4 kraw = *(const uint4*)(g_kh + (size_t)sC * D + ch * 8);
        uint4 vraw = *(const uint4*)(g_vh + (size_t)sC * D + ch * 8);

        __half2 a = __hmul2(*(__half2*)&kraw.x, q0);
        a = __hfma2(*(__half2*)&kraw.y, q1, a);
        a = __hfma2(*(__half2*)&kraw.z, q2, a);
        a = __hfma2(*(__half2*)&kraw.w, q3, a);
        float2 f = __half22float2(a);
        float sdot = f.x + f.y;
        sdot += __shfl_xor_sync(0xffffffffu, sdot, 4);
        sdot += __shfl_xor_sync(0xffffffffu, sdot, 2);
        sdot += __shfl_xor_sync(0xffffffffu, sdot, 1);

        float ex = ok ? __expf(sdot) : 0.0f;
        den += ex;
        if (ok && ch == 0) g_exc[idx] = ex;

        float2 v0 = __half22float2(*(__half2*)&vraw.x);
        float2 v1 = __half22float2(*(__half2*)&vraw.y);
        float2 v2 = __half22float2(*(__half2*)&vraw.z);
        float2 v3 = __half22float2(*(__half2*)&vraw.w);
        acc[0] += ex * v0.x; acc[1] += ex * v0.y;
        acc[2] += ex * v1.x; acc[3] += ex * v1.y;
        acc[4] += ex * v2.x; acc[5] += ex * v2.y;
        acc[6] += ex * v3.x; acc[7] += ex * v3.y;
    }

    den += __shfl_xor_sync(0xffffffffu, den, 8);
    den += __shfl_xor_sync(0xffffffffu, den, 16);
    #pragma unroll
    for (int j = 0; j < 8; j++) {
        acc[j] += __shfl_xor_sync(0xffffffffu, acc[j], 8);
        acc[j] += __shfl_xor_sync(0xffffffffu, acc[j], 16);
    }
    float rden = (den > 0.0f) ? 1.0f / den : 0.0f;

    if (grp == 0) {
        float4 h0 = make_float4(acc[0] * rden, acc[1] * rden, acc[2] * rden, acc[3] * rden);
        float4 h1 = make_float4(acc[4] * rden, acc[5] * rden, acc[6] * rden, acc[7] * rden);
        *(float4*)(h + (size_t)w * D + ch * 8)     = h0;
        *(float4*)(h + (size_t)w * D + ch * 8 + 4) = h1;
    }

    // alpha writeback: coalesced eid + exc reads, scattered 4B stores
    for (int j = lane; j < cnt; j += 32) {
        exbuf[g_eids[beg + j]] = g_exc[beg + j] * rden;
    }
}

// ---------------------------------------------------------------------------
// Launch. Inputs: z, Wq, bq, Wk, bk, Wv, bv, src, dst.
// Output: h [N,64] floats followed by alpha [E] floats.
// proj forked onto a second stream (captured fork-join); CSR chain on main.
// ---------------------------------------------------------------------------
extern "C" void kernel_launch(void* const* d_in, const int* in_sizes, int n_in,
                              void* d_out, int out_size)
{
    const float* z  = (const float*)d_in[0];
    const float* Wq = (const float*)d_in[1];
    const float* bq = (const float*)d_in[2];
    const float* Wk = (const float*)d_in[3];
    const float* bk = (const float*)d_in[4];
    const float* Wv = (const float*)d_in[5];
    const float* bv = (const float*)d_in[6];
    const int*  src = (const int*)d_in[7];
    const int*  dst = (const int*)d_in[8];

    const int n = in_sizes[0] / D;
    const int E = in_sizes[7];

    float* out = (float*)d_out;

    float* exbuf;
    if ((long long)out_size >= (long long)n * D + (long long)E) {
        exbuf = out + (size_t)n * D;
    } else {
        void* p = nullptr;
        cudaGetSymbolAddress(&p, g_ex);
        exbuf = (float*)p;
    }

    static cudaStream_t s1 = nullptr;
    static cudaEvent_t evF = nullptr, evJ = nullptr;
    if (s1 == nullptr) {
        cudaStreamCreateWithFlags(&s1, cudaStreamNonBlocking);
        cudaEventCreateWithFlags(&evF, cudaEventDisableTiming);
        cudaEventCreateWithFlags(&evJ, cudaEventDisableTiming);
    }

    const int len   = n + 1;
    const int nblk  = (len + SCAN_B - 1) / SCAN_B;
    const int eblk4 = (E + 1023) / 1024;   // 4 edges/thread, 256 threads

    // Fork: proj on s1, CSR chain on the main (capturing) stream.
    cudaEventRecord(evF, 0);
    cudaStreamWaitEvent(s1, evF, 0);
    proj_kernel<<<(n + 63) / 64, 256, 0, s1>>>(z, Wq, bq, Wk, bk, Wv, bv, n);
    cudaEventRecord(evJ, s1);

    hist_kernel<<<eblk4, 256>>>(dst, E);
    scan1_kernel<<<nblk, SCAN_B>>>(len);
    scan3_kernel<<<nblk, SCAN_B>>>(len);
    scatter_kernel<<<eblk4, 256>>>(src, dst, E, n);

    // Join: fused needs both q/k/v (s1) and the CSR (main).
    cudaStreamWaitEvent(0, evJ, 0);
    fused_attn_kernel<<<(n + 7) / 8, 256>>>(exbuf, out, n);
}

// round 14
// speedup vs baseline: 1.0435x; 1.0435x over previous
#include <cuda_runtime.h>
#include <cuda_fp16.h>
#include <math.h>

#define MAX_N 100000
#define MAX_E 1600000
#define D 64
#define SCAN_B 1024
#define ECAP 768   // staged edge records per block (6KB smem); global fallback

// ---- device scratch (no cudaMalloc allowed) --------------------------------
// g_count is zero at module load; scatter_kernel re-zeroes it every launch
// (after its last reader ran), so every launch sees zeros.
__device__ __align__(16) __half g_qh[MAX_N * D];   // q  fp16, 128B/row
__device__ __align__(16) __half g_kh[MAX_N * D];   // k*tau fp16
__device__ __align__(16) __half g_vh[MAX_N * D];   // v  fp16
__device__ int   g_count[MAX_N + 1];
__device__ int   g_rowptr[MAX_N + 1];
__device__ int   g_cursor[MAX_N + 1];
__device__ int   g_bsum[128];
__device__ int2  g_edges[MAX_E];        // (src, orig_eid) clustered by dst
__device__ float g_exc[MAX_E];          // ex in CSR order (coalesced)
__device__ float g_ex[MAX_E];           // fallback if out has no alpha slot

// ---- packed fp32x2 helpers (Blackwell FFMA2; ptxas never auto-fuses) -------
__device__ __forceinline__ void ffma2(unsigned long long& d,
                                      unsigned long long a,
                                      unsigned long long b) {
    asm("fma.rn.f32x2 %0, %1, %2, %0;" : "+l"(d) : "l"(a), "l"(b));
}
__device__ __forceinline__ unsigned long long pack2(float lo, float hi) {
    unsigned long long r;
    asm("mov.b64 %0, {%1, %2};" : "=l"(r) : "f"(lo), "f"(hi));
    return r;
}
__device__ __forceinline__ float2 unpack2(unsigned long long a) {
    float2 u;
    asm("mov.b64 {%0, %1}, %2;" : "=f"(u.x), "=f"(u.y) : "l"(a));
    return u;
}

// ---------------------------------------------------------------------------
// K1: q,k,v = z @ W{q,k,v} + b — exact fp32 via packed FFMA2 with NODE-PAIR
// packing (natural LDS.128 z operand, no tile duplication). Per k-step:
// 2x LDS.128 + 4 mov.b64 + 8 FFMA2. tau folded into k; outputs fp16 rows.
// ---------------------------------------------------------------------------
__global__ __launch_bounds__(256) void proj_kernel(
    const float* __restrict__ z,
    const float* __restrict__ Wq, const float* __restrict__ bq,
    const float* __restrict__ Wk, const float* __restrict__ bk,
    const float* __restrict__ Wv, const float* __restrict__ bv,
    int n)
{
    __shared__ __align__(16) float zsh[64 * 68];   // transposed: zsh[k*68 + node]
    __shared__ __align__(16) float wsh[64 * 64];   // wsh[k*64 + dim]

    const int tid = threadIdx.x;
    const int node0 = blockIdx.x * 64;

    for (int i = tid; i < 64 * 64; i += 256) {
        int nn = i >> 6, kk = i & 63;
        int g = node0 + nn;
        zsh[kk * 68 + nn] = (g < n) ? z[(size_t)g * D + kk] : 0.0f;
    }

    const float* Ws[3] = {Wq, Wk, Wv};
    const float* bs[3] = {bq, bk, bv};
    __half* outs[3] = {g_qh, g_kh, g_vh};

    const int ng = tid >> 4;   // node group 0..15 (4 nodes = 2 node-pairs)
    const int dg = tid & 15;   // dim  group 0..15 (4 dims)

    for (int p = 0; p < 3; p++) {
        __syncthreads();
        const float* W = Ws[p];
        for (int i = tid; i < 64 * 64; i += 256) wsh[i] = W[i];
        __syncthreads();

        float4 b4 = *(const float4*)(bs[p] + dg * 4);
        unsigned long long acc2[2][4];
        acc2[0][0] = acc2[1][0] = pack2(b4.x, b4.x);
        acc2[0][1] = acc2[1][1] = pack2(b4.y, b4.y);
        acc2[0][2] = acc2[1][2] = pack2(b4.z, b4.z);
        acc2[0][3] = acc2[1][3] = pack2(b4.w, b4.w);

        #pragma unroll 8
        for (int k = 0; k < 64; k++) {
            ulonglong2 zz = *(const ulonglong2*)&zsh[k * 68 + ng * 4];
            float4 wv = *(const float4*)&wsh[k * 64 + dg * 4];
            unsigned long long w0 = pack2(wv.x, wv.x);
            unsigned long long w1 = pack2(wv.y, wv.y);
            unsigned long long w2 = pack2(wv.z, wv.z);
            unsigned long long w3 = pack2(wv.w, wv.w);
            ffma2(acc2[0][0], zz.x, w0); ffma2(acc2[0][1], zz.x, w1);
            ffma2(acc2[0][2], zz.x, w2); ffma2(acc2[0][3], zz.x, w3);
            ffma2(acc2[1][0], zz.y, w0); ffma2(acc2[1][1], zz.y, w1);
            ffma2(acc2[1][2], zz.y, w2); ffma2(acc2[1][3], zz.y, w3);
        }

        const float scl = (p == 1) ? 0.125f : 1.0f;   // tau into k
        __half* op = outs[p];
        #pragma unroll
        for (int i2 = 0; i2 < 4; i2++) {
            int g = node0 + ng * 4 + i2;
            if (g < n) {
                int pr = i2 >> 1, lo = i2 & 1;
                float2 d0 = unpack2(acc2[pr][0]);
                float2 d1 = unpack2(acc2[pr][1]);
                float2 d2 = unpack2(acc2[pr][2]);
                float2 d3 = unpack2(acc2[pr][3]);
                float e0 = lo ? d0.y : d0.x;
                float e1 = lo ? d1.y : d1.x;
                float e2 = lo ? d2.y : d2.x;
                float e3 = lo ? d3.y : d3.x;
                __half2 h01 = __float22half2_rn(make_float2(e0 * scl, e1 * scl));
                __half2 h23 = __float22half2_rn(make_float2(e2 * scl, e3 * scl));
                uint2 pk;
                pk.x = *(unsigned*)&h01; pk.y = *(unsigned*)&h23;
                *(uint2*)(op + (size_t)g * D + dg * 4) = pk;
            }
        }
    }
}

// ---------------------------------------------------------------------------
// CSR build: hist (int4) -> scan1 (block sums) -> scan3 (scan + per-block
// bsum prefix) -> scatter (int4, also re-zeroes g_count for next launch).
// ---------------------------------------------------------------------------
__global__ void hist_kernel(const int* __restrict__ dst, int E) {
    int e = (blockIdx.x * blockDim.x + threadIdx.x) * 4;
    if (e + 3 < E) {
        int4 d = *(const int4*)(dst + e);
        atomicAdd(&g_count[d.x], 1);
        atomicAdd(&g_count[d.y], 1);
        atomicAdd(&g_count[d.z], 1);
        atomicAdd(&g_count[d.w], 1);
    } else {
        for (int t = e; t < E; t++) atomicAdd(&g_count[dst[t]], 1);
    }
}

__global__ __launch_bounds__(SCAN_B) void scan1_kernel(int len) {
    __shared__ int wsum[32];
    int t = threadIdx.x, lane = t & 31, wid = t >> 5;
    int i = blockIdx.x * SCAN_B + t;
    int v = (i < len) ? g_count[i] : 0;
    #pragma unroll
    for (int off = 16; off > 0; off >>= 1) v += __shfl_xor_sync(0xffffffffu, v, off);
    if (lane == 0) wsum[wid] = v;
    __syncthreads();
    if (wid == 0) {
        int x = wsum[lane];
        #pragma unroll
        for (int off = 16; off > 0; off >>= 1) x += __shfl_xor_sync(0xffffffffu, x, off);
        if (lane == 0) g_bsum[blockIdx.x] = x;
    }
}

__global__ __launch_bounds__(SCAN_B) void scan3_kernel(int len) {
    __shared__ int wsum[32];
    __shared__ int blk_off;
    int t = threadIdx.x, lane = t & 31, wid = t >> 5;

    if (wid == 0) {
        int s = 0;
        for (int b = lane; b < blockIdx.x; b += 32) s += g_bsum[b];
        #pragma unroll
        for (int off = 16; off > 0; off >>= 1) s += __shfl_xor_sync(0xffffffffu, s, off);
        if (lane == 0) blk_off = s;
    }

    int i = blockIdx.x * SCAN_B + t;
    int v = (i < len) ? g_count[i] : 0;
    int incl = v;
    #pragma unroll
    for (int off = 1; off < 32; off <<= 1) {
        int u = __shfl_up_sync(0xffffffffu, incl, off);
        if (lane >= off) incl += u;
    }
    if (lane == 31) wsum[wid] = incl;
    __syncthreads();
    if (wid == 0) {
        int x = wsum[lane];
        #pragma unroll
        for (int off = 1; off < 32; off <<= 1) {
            int u = __shfl_up_sync(0xffffffffu, x, off);
            if (lane >= off) x += u;
        }
        wsum[lane] = x;
    }
    __syncthreads();
    int excl = incl - v + ((wid > 0) ? wsum[wid - 1] : 0) + blk_off;
    if (i < len) { g_rowptr[i] = excl; g_cursor[i] = excl; }
}

__global__ void scatter_kernel(const int* __restrict__ src,
                               const int* __restrict__ dst, int E, int n) {
    int gt = blockIdx.x * blockDim.x + threadIdx.x;
    if (gt <= n) g_count[gt] = 0;   // re-zero histogram for next launch

    int e = gt * 4;
    if (e + 3 < E) {
        int4 s = *(const int4*)(src + e);
        int4 d = *(const int4*)(dst + e);
        int p0 = atomicAdd(&g_cursor[d.x], 1);
        int p1 = atomicAdd(&g_cursor[d.y], 1);
        int p2 = atomicAdd(&g_cursor[d.z], 1);
        int p3 = atomicAdd(&g_cursor[d.w], 1);
        g_edges[p0] = make_int2(s.x, e + 0);
        g_edges[p1] = make_int2(s.y, e + 1);
        g_edges[p2] = make_int2(s.z, e + 2);
        g_edges[p3] = make_int2(s.w, e + 3);
    } else {
        for (int t = e; t < E; t++) {
            int pos = atomicAdd(&g_cursor[dst[t]], 1);
            g_edges[pos] = make_int2(src[t], t);
        }
    }
}

// ---------------------------------------------------------------------------
// K2 (fused): one warp per dst node, 8 lanes per edge, 4 edges per iteration.
// The block's 8 nodes own a CONTIGUOUS CSR slice -> stage all its edge
// records into smem once (coalesced), so the per-edge record read is an LDS
// (29cyc) instead of a dependent 250cyc L2 round trip. Global fallback past
// ECAP (deterministic). fp16 HFMA2 dot (tau in k), fp32 accumulation.
// ex coalesced to CSR buffer; epilogue scatters alpha=ex*rden, stores h.
// NO atomics. Segment-max skipped: alpha shift-invariant, |e|<~6 -> exp safe.
// ---------------------------------------------------------------------------
__global__ __launch_bounds__(256) void fused_attn_kernel(
    float* __restrict__ exbuf, float* __restrict__ h, int n)
{
    __shared__ int2 s_edges[ECAP];

    int tid = threadIdx.x;
    int wid = tid >> 5;
    int w0 = blockIdx.x * 8;
    int w  = w0 + wid;

    int wlast = (w0 + 8 < n) ? (w0 + 8) : n;
    int blkbeg = __ldg(&g_rowptr[w0]);
    int blkend = __ldg(&g_rowptr[wlast]);
    int total  = blkend - blkbeg;
    int staged = (total < ECAP) ? total : ECAP;

    for (int j = tid; j < staged; j += 256)
        s_edges[j] = g_edges[blkbeg + j];
    __syncthreads();

    if (w >= n) return;

    int lane = tid & 31;
    int grp  = lane >> 3;        // edge group 0..3
    int ch   = lane & 7;         // 8-half chunk of the 64-dim row

    int beg = __ldg(&g_rowptr[w]);
    int end = __ldg(&g_rowptr[w + 1]);
    int cnt = end - beg;

    uint4 qraw = *(const uint4*)(g_qh + (size_t)w * D + ch * 8);
    __half2 q0 = *(__half2*)&qraw.x, q1 = *(__half2*)&qraw.y,
            q2 = *(__half2*)&qraw.z, q3 = *(__half2*)&qraw.w;

    float den = 0.0f;
    float acc[8];
    #pragma unroll
    for (int j = 0; j < 8; j++) acc[j] = 0.0f;

    for (int i = beg; i < end; i += 4) {
        int idx = i + grp;
        bool ok = idx < end;
        int rel = idx - blkbeg;
        if (rel >= total) rel = total - 1;           // clamp for !ok lanes
        int2 er = (rel < staged) ? s_edges[rel] : g_edges[blkbeg + rel];
        int s = er.x;

        uint4 kraw = *(const uint4*)(g_kh + (size_t)s * D + ch * 8);
        uint4 vraw = *(const uint4*)(g_vh + (size_t)s * D + ch * 8);

        __half2 a = __hmul2(*(__half2*)&kraw.x, q0);
        a = __hfma2(*(__half2*)&kraw.y, q1, a);
        a = __hfma2(*(__half2*)&kraw.z, q2, a);
        a = __hfma2(*(__half2*)&kraw.w, q3, a);
        float2 f = __half22float2(a);
        float sdot = f.x + f.y;
        sdot += __shfl_xor_sync(0xffffffffu, sdot, 4);
        sdot += __shfl_xor_sync(0xffffffffu, sdot, 2);
        sdot += __shfl_xor_sync(0xffffffffu, sdot, 1);

        float ex = ok ? __expf(sdot) : 0.0f;
        den += ex;
        if (ok && ch == 0) g_exc[idx] = ex;

        float2 v0 = __half22float2(*(__half2*)&vraw.x);
        float2 v1 = __half22float2(*(__half2*)&vraw.y);
        float2 v2 = __half22float2(*(__half2*)&vraw.z);
        float2 v3 = __half22float2(*(__half2*)&vraw.w);
        acc[0] += ex * v0.x; acc[1] += ex * v0.y;
        acc[2] += ex * v1.x; acc[3] += ex * v1.y;
        acc[4] += ex * v2.x; acc[5] += ex * v2.y;
        acc[6] += ex * v3.x; acc[7] += ex * v3.y;
    }

    den += __shfl_xor_sync(0xffffffffu, den, 8);
    den += __shfl_xor_sync(0xffffffffu, den, 16);
    #pragma unroll
    for (int j = 0; j < 8; j++) {
        acc[j] += __shfl_xor_sync(0xffffffffu, acc[j], 8);
        acc[j] += __shfl_xor_sync(0xffffffffu, acc[j], 16);
    }
    float rden = (den > 0.0f) ? 1.0f / den : 0.0f;

    if (grp == 0) {
        float4 h0 = make_float4(acc[0] * rden, acc[1] * rden, acc[2] * rden, acc[3] * rden);
        float4 h1 = make_float4(acc[4] * rden, acc[5] * rden, acc[6] * rden, acc[7] * rden);
        *(float4*)(h + (size_t)w * D + ch * 8)     = h0;
        *(float4*)(h + (size_t)w * D + ch * 8 + 4) = h1;
    }

    // alpha writeback: records from smem, exc coalesced, scattered 4B stores
    for (int j = lane; j < cnt; j += 32) {
        int rel = beg - blkbeg + j;
        int eid = (rel < staged) ? s_edges[rel].y : g_edges[blkbeg + rel].y;
        exbuf[eid] = g_exc[beg + j] * rden;
    }
}

// ---------------------------------------------------------------------------
// Launch. Inputs: z, Wq, bq, Wk, bk, Wv, bv, src, dst.
// Output: h [N,64] floats followed by alpha [E] floats.
// proj forked onto a second stream (captured fork-join); CSR chain on main.
// ---------------------------------------------------------------------------
extern "C" void kernel_launch(void* const* d_in, const int* in_sizes, int n_in,
                              void* d_out, int out_size)
{
    const float* z  = (const float*)d_in[0];
    const float* Wq = (const float*)d_in[1];
    const float* bq = (const float*)d_in[2];
    const float* Wk = (const float*)d_in[3];
    const float* bk = (const float*)d_in[4];
    const float* Wv = (const float*)d_in[5];
    const float* bv = (const float*)d_in[6];
    const int*  src = (const int*)d_in[7];
    const int*  dst = (const int*)d_in[8];

    const int n = in_sizes[0] / D;
    const int E = in_sizes[7];

    float* out = (float*)d_out;

    float* exbuf;
    if ((long long)out_size >= (long long)n * D + (long long)E) {
        exbuf = out + (size_t)n * D;
    } else {
        void* p = nullptr;
        cudaGetSymbolAddress(&p, g_ex);
        exbuf = (float*)p;
    }

    static cudaStream_t s1 = nullptr;
    static cudaEvent_t evF = nullptr, evJ = nullptr;
    if (s1 == nullptr) {
        cudaStreamCreateWithFlags(&s1, cudaStreamNonBlocking);
        cudaEventCreateWithFlags(&evF, cudaEventDisableTiming);
        cudaEventCreateWithFlags(&evJ, cudaEventDisableTiming);
    }

    const int len   = n + 1;
    const int nblk  = (len + SCAN_B - 1) / SCAN_B;
    const int eblk4 = (E + 1023) / 1024;   // 4 edges/thread, 256 threads

    // Fork: proj on s1, CSR chain on the main (capturing) stream.
    cudaEventRecord(evF, 0);
    cudaStreamWaitEvent(s1, evF, 0);
    proj_kernel<<<(n + 63) / 64, 256, 0, s1>>>(z, Wq, bq, Wk, bk, Wv, bv, n);
    cudaEventRecord(evJ, s1);

    hist_kernel<<<eblk4, 256>>>(dst, E);
    scan1_kernel<<<nblk, SCAN_B>>>(len);
    scan3_kernel<<<nblk, SCAN_B>>>(len);
    scatter_kernel<<<eblk4, 256>>>(src, dst, E, n);

    // Join: fused needs both q/k/v (s1) and the CSR (main).
    cudaStreamWaitEvent(0, evJ, 0);
    fused_attn_kernel<<<(n + 7) / 8, 256>>>(exbuf, out, n);
}

// round 15
// speedup vs baseline: 1.0713x; 1.0267x over previous
#include <cuda_runtime.h>
#include <cuda_fp16.h>
#include <math.h>

#define MAX_N 100000
#define MAX_E 1600000
#define D 64
#define SCAN_B 1024
#define FUSED_BLOCKS 1184           // 148 SMs x 8 blocks, 8 warps each

// ---- device scratch (no cudaMalloc allowed) --------------------------------
// g_count is zero at module load; scatter_kernel re-zeroes it every launch
// (after its last reader ran), so every launch sees zeros.
__device__ __align__(16) __half g_qh[MAX_N * D];   // q  fp16, 128B/row
__device__ __align__(16) __half g_kh[MAX_N * D];   // k*tau fp16
__device__ __align__(16) __half g_vh[MAX_N * D];   // v  fp16
__device__ int   g_count[MAX_N + 1];
__device__ int   g_rowptr[MAX_N + 1];
__device__ int   g_cursor[MAX_N + 1];
__device__ int   g_bsum[128];
__device__ int2  g_edges[MAX_E];        // (src, orig_eid) clustered by dst
__device__ float g_exc[MAX_E];          // ex in CSR order (coalesced)
__device__ float g_ex[MAX_E];           // fallback if out has no alpha slot

// ---- packed fp32x2 helpers (Blackwell FFMA2; ptxas never auto-fuses) -------
__device__ __forceinline__ void ffma2(unsigned long long& d,
                                      unsigned long long a,
                                      unsigned long long b) {
    asm("fma.rn.f32x2 %0, %1, %2, %0;" : "+l"(d) : "l"(a), "l"(b));
}
__device__ __forceinline__ unsigned long long pack2(float lo, float hi) {
    unsigned long long r;
    asm("mov.b64 %0, {%1, %2};" : "=l"(r) : "f"(lo), "f"(hi));
    return r;
}
__device__ __forceinline__ float2 unpack2(unsigned long long a) {
    float2 u;
    asm("mov.b64 {%0, %1}, %2;" : "=f"(u.x), "=f"(u.y) : "l"(a));
    return u;
}

// ---------------------------------------------------------------------------
// K1: q,k,v = z @ W{q,k,v} + b — exact fp32 via packed FFMA2 with NODE-PAIR
// packing (natural LDS.128 z operand, no tile duplication). Per k-step:
// 2x LDS.128 + 4 mov.b64 + 8 FFMA2. tau folded into k; outputs fp16 rows.
// ---------------------------------------------------------------------------
__global__ __launch_bounds__(256) void proj_kernel(
    const float* __restrict__ z,
    const float* __restrict__ Wq, const float* __restrict__ bq,
    const float* __restrict__ Wk, const float* __restrict__ bk,
    const float* __restrict__ Wv, const float* __restrict__ bv,
    int n)
{
    __shared__ __align__(16) float zsh[64 * 68];   // transposed: zsh[k*68 + node]
    __shared__ __align__(16) float wsh[64 * 64];   // wsh[k*64 + dim]

    const int tid = threadIdx.x;
    const int node0 = blockIdx.x * 64;

    for (int i = tid; i < 64 * 64; i += 256) {
        int nn = i >> 6, kk = i & 63;
        int g = node0 + nn;
        zsh[kk * 68 + nn] = (g < n) ? z[(size_t)g * D + kk] : 0.0f;
    }

    const float* Ws[3] = {Wq, Wk, Wv};
    const float* bs[3] = {bq, bk, bv};
    __half* outs[3] = {g_qh, g_kh, g_vh};

    const int ng = tid >> 4;   // node group 0..15 (4 nodes = 2 node-pairs)
    const int dg = tid & 15;   // dim  group 0..15 (4 dims)

    for (int p = 0; p < 3; p++) {
        __syncthreads();
        const float* W = Ws[p];
        for (int i = tid; i < 64 * 64; i += 256) wsh[i] = W[i];
        __syncthreads();

        float4 b4 = *(const float4*)(bs[p] + dg * 4);
        unsigned long long acc2[2][4];
        acc2[0][0] = acc2[1][0] = pack2(b4.x, b4.x);
        acc2[0][1] = acc2[1][1] = pack2(b4.y, b4.y);
        acc2[0][2] = acc2[1][2] = pack2(b4.z, b4.z);
        acc2[0][3] = acc2[1][3] = pack2(b4.w, b4.w);

        #pragma unroll 8
        for (int k = 0; k < 64; k++) {
            ulonglong2 zz = *(const ulonglong2*)&zsh[k * 68 + ng * 4];
            float4 wv = *(const float4*)&wsh[k * 64 + dg * 4];
            unsigned long long w0 = pack2(wv.x, wv.x);
            unsigned long long w1 = pack2(wv.y, wv.y);
            unsigned long long w2 = pack2(wv.z, wv.z);
            unsigned long long w3 = pack2(wv.w, wv.w);
            ffma2(acc2[0][0], zz.x, w0); ffma2(acc2[0][1], zz.x, w1);
            ffma2(acc2[0][2], zz.x, w2); ffma2(acc2[0][3], zz.x, w3);
            ffma2(acc2[1][0], zz.y, w0); ffma2(acc2[1][1], zz.y, w1);
            ffma2(acc2[1][2], zz.y, w2); ffma2(acc2[1][3], zz.y, w3);
        }

        const float scl = (p == 1) ? 0.125f : 1.0f;   // tau into k
        __half* op = outs[p];
        #pragma unroll
        for (int i2 = 0; i2 < 4; i2++) {
            int g = node0 + ng * 4 + i2;
            if (g < n) {
                int pr = i2 >> 1, lo = i2 & 1;
                float2 d0 = unpack2(acc2[pr][0]);
                float2 d1 = unpack2(acc2[pr][1]);
                float2 d2 = unpack2(acc2[pr][2]);
                float2 d3 = unpack2(acc2[pr][3]);
                float e0 = lo ? d0.y : d0.x;
                float e1 = lo ? d1.y : d1.x;
                float e2 = lo ? d2.y : d2.x;
                float e3 = lo ? d3.y : d3.x;
                __half2 h01 = __float22half2_rn(make_float2(e0 * scl, e1 * scl));
                __half2 h23 = __float22half2_rn(make_float2(e2 * scl, e3 * scl));
                uint2 pk;
                pk.x = *(unsigned*)&h01; pk.y = *(unsigned*)&h23;
                *(uint2*)(op + (size_t)g * D + dg * 4) = pk;
            }
        }
    }
}

// ---------------------------------------------------------------------------
// CSR build: hist (int4) -> scan1 (block sums) -> scan3 (scan + per-block
// bsum prefix) -> scatter (int4, also re-zeroes g_count for next launch).
// ---------------------------------------------------------------------------
__global__ void hist_kernel(const int* __restrict__ dst, int E) {
    int e = (blockIdx.x * blockDim.x + threadIdx.x) * 4;
    if (e + 3 < E) {
        int4 d = *(const int4*)(dst + e);
        atomicAdd(&g_count[d.x], 1);
        atomicAdd(&g_count[d.y], 1);
        atomicAdd(&g_count[d.z], 1);
        atomicAdd(&g_count[d.w], 1);
    } else {
        for (int t = e; t < E; t++) atomicAdd(&g_count[dst[t]], 1);
    }
}

__global__ __launch_bounds__(SCAN_B) void scan1_kernel(int len) {
    __shared__ int wsum[32];
    int t = threadIdx.x, lane = t & 31, wid = t >> 5;
    int i = blockIdx.x * SCAN_B + t;
    int v = (i < len) ? g_count[i] : 0;
    #pragma unroll
    for (int off = 16; off > 0; off >>= 1) v += __shfl_xor_sync(0xffffffffu, v, off);
    if (lane == 0) wsum[wid] = v;
    __syncthreads();
    if (wid == 0) {
        int x = wsum[lane];
        #pragma unroll
        for (int off = 16; off > 0; off >>= 1) x += __shfl_xor_sync(0xffffffffu, x, off);
        if (lane == 0) g_bsum[blockIdx.x] = x;
    }
}

__global__ __launch_bounds__(SCAN_B) void scan3_kernel(int len) {
    __shared__ int wsum[32];
    __shared__ int blk_off;
    int t = threadIdx.x, lane = t & 31, wid = t >> 5;

    if (wid == 0) {
        int s = 0;
        for (int b = lane; b < blockIdx.x; b += 32) s += g_bsum[b];
        #pragma unroll
        for (int off = 16; off > 0; off >>= 1) s += __shfl_xor_sync(0xffffffffu, s, off);
        if (lane == 0) blk_off = s;
    }

    int i = blockIdx.x * SCAN_B + t;
    int v = (i < len) ? g_count[i] : 0;
    int incl = v;
    #pragma unroll
    for (int off = 1; off < 32; off <<= 1) {
        int u = __shfl_up_sync(0xffffffffu, incl, off);
        if (lane >= off) incl += u;
    }
    if (lane == 31) wsum[wid] = incl;
    __syncthreads();
    if (wid == 0) {
        int x = wsum[lane];
        #pragma unroll
        for (int off = 1; off < 32; off <<= 1) {
            int u = __shfl_up_sync(0xffffffffu, x, off);
            if (lane >= off) x += u;
        }
        wsum[lane] = x;
    }
    __syncthreads();
    int excl = incl - v + ((wid > 0) ? wsum[wid - 1] : 0) + blk_off;
    if (i < len) { g_rowptr[i] = excl; g_cursor[i] = excl; }
}

__global__ void scatter_kernel(const int* __restrict__ src,
                               const int* __restrict__ dst, int E, int n) {
    int gt = blockIdx.x * blockDim.x + threadIdx.x;
    if (gt <= n) g_count[gt] = 0;   // re-zero histogram for next launch

    int e = gt * 4;
    if (e + 3 < E) {
        int4 s = *(const int4*)(src + e);
        int4 d = *(const int4*)(dst + e);
        int p0 = atomicAdd(&g_cursor[d.x], 1);
        int p1 = atomicAdd(&g_cursor[d.y], 1);
        int p2 = atomicAdd(&g_cursor[d.z], 1);
        int p3 = atomicAdd(&g_cursor[d.w], 1);
        g_edges[p0] = make_int2(s.x, e + 0);
        g_edges[p1] = make_int2(s.y, e + 1);
        g_edges[p2] = make_int2(s.z, e + 2);
        g_edges[p3] = make_int2(s.w, e + 3);
    } else {
        for (int t = e; t < E; t++) {
            int pos = atomicAdd(&g_cursor[dst[t]], 1);
            g_edges[pos] = make_int2(src[t], t);
        }
    }
}

// ---------------------------------------------------------------------------
// K2 (fused, PERSISTENT): fixed grid, each warp grid-strides over ~10 nodes;
// next node's rowptr pair + q row are prefetched before the current node's
// edge loop so the per-node startup chain is hidden. Inner loop identical to
// the 203.2 baseline: 8 lanes/edge, 4 edges/iter, fp16 HFMA2 dot (tau in k),
// fp32 accumulation, ex coalesced to CSR buffer, alpha scattered in epilogue.
// NO atomics, NO smem. Segment-max skipped: |e|<~6 -> exp safe.
// ---------------------------------------------------------------------------
__global__ __launch_bounds__(256) void fused_attn_kernel(
    float* __restrict__ exbuf, float* __restrict__ h, int n)
{
    const int nwarps = FUSED_BLOCKS * 8;
    int gwarp = blockIdx.x * 8 + (threadIdx.x >> 5);
    if (gwarp >= n) return;
    int lane = threadIdx.x & 31;
    int grp  = lane >> 3;        // edge group 0..3
    int ch   = lane & 7;         // 8-half chunk of the 64-dim row

    // current node state (loaded once; thereafter arrives via prefetch)
    int w   = gwarp;
    int beg = __ldg(&g_rowptr[w]);
    int end = __ldg(&g_rowptr[w + 1]);
    uint4 qraw = *(const uint4*)(g_qh + (size_t)w * D + ch * 8);

    while (true) {
        // ---- prefetch next node's state (consumed after this node) ----
        int wn = w + nwarps;
        int begN = 0, endN = 0;
        uint4 qrawN = make_uint4(0u, 0u, 0u, 0u);
        if (wn < n) {
            begN  = __ldg(&g_rowptr[wn]);
            endN  = __ldg(&g_rowptr[wn + 1]);
            qrawN = *(const uint4*)(g_qh + (size_t)wn * D + ch * 8);
        }

        // ---- process node w ----
        __half2 q0 = *(__half2*)&qraw.x, q1 = *(__half2*)&qraw.y,
                q2 = *(__half2*)&qraw.z, q3 = *(__half2*)&qraw.w;
        int cnt = end - beg;

        float den = 0.0f;
        float acc[8];
        #pragma unroll
        for (int j = 0; j < 8; j++) acc[j] = 0.0f;

        for (int i = beg; i < end; i += 4) {
            int idx = i + grp;
            bool ok = idx < end;
            int2 er = g_edges[ok ? idx : end - 1];
            int s = er.x;

            uint4 kraw = *(const uint4*)(g_kh + (size_t)s * D + ch * 8);
            uint4 vraw = *(const uint4*)(g_vh + (size_t)s * D + ch * 8);

            __half2 a = __hmul2(*(__half2*)&kraw.x, q0);
            a = __hfma2(*(__half2*)&kraw.y, q1, a);
            a = __hfma2(*(__half2*)&kraw.z, q2, a);
            a = __hfma2(*(__half2*)&kraw.w, q3, a);
            float2 f = __half22float2(a);
            float sdot = f.x + f.y;
            sdot += __shfl_xor_sync(0xffffffffu, sdot, 4);
            sdot += __shfl_xor_sync(0xffffffffu, sdot, 2);
            sdot += __shfl_xor_sync(0xffffffffu, sdot, 1);

            float ex = ok ? __expf(sdot) : 0.0f;
            den += ex;
            if (ok && ch == 0) g_exc[idx] = ex;

            float2 v0 = __half22float2(*(__half2*)&vraw.x);
            float2 v1 = __half22float2(*(__half2*)&vraw.y);
            float2 v2 = __half22float2(*(__half2*)&vraw.z);
            float2 v3 = __half22float2(*(__half2*)&vraw.w);
            acc[0] += ex * v0.x; acc[1] += ex * v0.y;
            acc[2] += ex * v1.x; acc[3] += ex * v1.y;
            acc[4] += ex * v2.x; acc[5] += ex * v2.y;
            acc[6] += ex * v3.x; acc[7] += ex * v3.y;
        }

        den += __shfl_xor_sync(0xffffffffu, den, 8);
        den += __shfl_xor_sync(0xffffffffu, den, 16);
        #pragma unroll
        for (int j = 0; j < 8; j++) {
            acc[j] += __shfl_xor_sync(0xffffffffu, acc[j], 8);
            acc[j] += __shfl_xor_sync(0xffffffffu, acc[j], 16);
        }
        float rden = (den > 0.0f) ? 1.0f / den : 0.0f;

        if (grp == 0) {
            float4 h0 = make_float4(acc[0] * rden, acc[1] * rden, acc[2] * rden, acc[3] * rden);
            float4 h1 = make_float4(acc[4] * rden, acc[5] * rden, acc[6] * rden, acc[7] * rden);
            *(float4*)(h + (size_t)w * D + ch * 8)     = h0;
            *(float4*)(h + (size_t)w * D + ch * 8 + 4) = h1;
        }

        // alpha writeback: coalesced exc reads, scattered 4B stores
        for (int j = lane; j < cnt; j += 32) {
            int eid = g_edges[beg + j].y;
            exbuf[eid] = g_exc[beg + j] * rden;
        }

        // ---- advance to prefetched node ----
        if (wn >= n) break;
        w = wn; beg = begN; end = endN; qraw = qrawN;
    }
}

// ---------------------------------------------------------------------------
// Launch. Inputs: z, Wq, bq, Wk, bk, Wv, bv, src, dst.
// Output: h [N,64] floats followed by alpha [E] floats.
// proj forked onto a second stream (captured fork-join); CSR chain on main.
// ---------------------------------------------------------------------------
extern "C" void kernel_launch(void* const* d_in, const int* in_sizes, int n_in,
                              void* d_out, int out_size)
{
    const float* z  = (const float*)d_in[0];
    const float* Wq = (const float*)d_in[1];
    const float* bq = (const float*)d_in[2];
    const float* Wk = (const float*)d_in[3];
    const float* bk = (const float*)d_in[4];
    const float* Wv = (const float*)d_in[5];
    const float* bv = (const float*)d_in[6];
    const int*  src = (const int*)d_in[7];
    const int*  dst = (const int*)d_in[8];

    const int n = in_sizes[0] / D;
    const int E = in_sizes[7];

    float* out = (float*)d_out;

    float* exbuf;
    if ((long long)out_size >= (long long)n * D + (long long)E) {
        exbuf = out + (size_t)n * D;
    } else {
        void* p = nullptr;
        cudaGetSymbolAddress(&p, g_ex);
        exbuf = (float*)p;
    }

    static cudaStream_t s1 = nullptr;
    static cudaEvent_t evF = nullptr, evJ = nullptr;
    if (s1 == nullptr) {
        cudaStreamCreateWithFlags(&s1, cudaStreamNonBlocking);
        cudaEventCreateWithFlags(&evF, cudaEventDisableTiming);
        cudaEventCreateWithFlags(&evJ, cudaEventDisableTiming);
    }

    const int len   = n + 1;
    const int nblk  = (len + SCAN_B - 1) / SCAN_B;
    const int eblk4 = (E + 1023) / 1024;   // 4 edges/thread, 256 threads

    // Fork: proj on s1, CSR chain on the main (capturing) stream.
    cudaEventRecord(evF, 0);
    cudaStreamWaitEvent(s1, evF, 0);
    proj_kernel<<<(n + 63) / 64, 256, 0, s1>>>(z, Wq, bq, Wk, bk, Wv, bv, n);
    cudaEventRecord(evJ, s1);

    hist_kernel<<<eblk4, 256>>>(dst, E);
    scan1_kernel<<<nblk, SCAN_B>>>(len);
    scan3_kernel<<<nblk, SCAN_B>>>(len);
    scatter_kernel<<<eblk4, 256>>>(src, dst, E, n);

    // Join: fused needs both q/k/v (s1) and the CSR (main).
    cudaStreamWaitEvent(0, evJ, 0);
    fused_attn_kernel<<<FUSED_BLOCKS, 256>>>(exbuf, out, n);
}